// round 5
// baseline (speedup 1.0000x reference)
#include <cuda_runtime.h>

// out = M rho M^T on the Hamming-weight-2 basis (N = C(32,2) = 496).
// M block-diagonal over 36 pair-blocks; only TWO distinct 4x4 tile matrices
// (V_row: params 0-5, V_col: params 6-11), fixed pyramid order {0,1,0,2,1,0}.
//   cross block (t1<t2): dim 16, B = V_t1 (x) V_t2
//   diag  block (t):     dim 6,  B = Lambda^2(V_t)  (computed inline)
// Grid = 1296 CTAs (one per (I,J) block), 64 threads. 3 barriers total;
// global gather issued before V-compose to hide DRAM latency.

#define NP 496

__device__ __forceinline__ int pair_idx(int a, int b) {
    return a * 31 - (a * (a - 1)) / 2 + (b - a - 1);
}

__device__ __forceinline__ void decode_block(int B, int& t1, int& t2, int& dim) {
    if (B < 28) {
        int rem = B, a = 0;
        while (rem >= 7 - a) { rem -= 7 - a; a++; }
        t1 = a; t2 = a + 1 + rem; dim = 16;
    } else {
        t1 = B - 28; t2 = t1; dim = 6;
    }
}

// P1 = {0,0,0,1,1,2}, P2 = {1,2,3,2,3,3}, 3 bits/entry
#define P1W 0x11200
#define P2W 0x1B4D1
__device__ __forceinline__ int p1of(int m) { return (P1W >> (3 * m)) & 7; }
__device__ __forceinline__ int p2of(int m) { return (P2W >> (3 * m)) & 7; }

template <int D>
__device__ __forceinline__ int gidx(int t1, int t2, int m) {
    if (D == 16) return pair_idx(4 * t1 + (m >> 2), 4 * t2 + (m & 3));
    return pair_idx(4 * t1 + p1of(m), 4 * t1 + p2of(m));
}

// Compose the two 4x4 tile matrices in registers; warp w handles params 6w..6w+5.
__device__ __forceinline__ void compose_V(int tid, const float* __restrict__ thetas,
                                          float sV[2][16]) {
    const int reg = tid >> 5;
    float v[4][4] = {{1,0,0,0},{0,1,0,0},{0,0,1,0},{0,0,0,1}};
    const int jseq[6] = {0, 1, 0, 2, 1, 0};
    #pragma unroll
    for (int gi = 0; gi < 6; gi++) {
        float s, c;
        sincosf(__ldg(thetas + reg * 6 + gi), &s, &c);
        const int j = jseq[gi];
        #pragma unroll
        for (int k = 0; k < 4; k++) {
            float a = v[j][k], b = v[j + 1][k];
            v[j][k]     = c * a + s * b;
            v[j + 1][k] = c * b - s * a;
        }
    }
    if ((tid & 31) == 0) {
        #pragma unroll
        for (int r = 0; r < 4; r++)
            #pragma unroll
            for (int c = 0; c < 4; c++) sV[reg][r * 4 + c] = v[r][c];
    }
}

// inline W row entry for diag blocks: W[m][n] from tile matrix U (4x4)
__device__ __forceinline__ float went(const float* U, int m, int n) {
    int a = p1of(m), b = p2of(m), g = p1of(n), d = p2of(n);
    return U[a * 4 + g] * U[b * 4 + d] - U[a * 4 + d] * U[b * 4 + g];
}

template <int DI, int DJ>
__device__ __forceinline__ void process(
    const float* __restrict__ rho, float* __restrict__ out,
    const float* __restrict__ thetas,
    int T1, int T2, int t1, int t2, int tid,
    float sV[2][16], float (*bufA)[20], float (*bufB)[20])
{
    // ---------------- per-thread ownership + EARLY global gather ------------
    float4 r4;                 // DJ==16: strip (m, 4g..4g+3)
    float rs[2];               // DJ==6 : up to 2 scalar elements
    int m_s = 0, g_s = 0, rowoff = 0, colbase = 0;
    const bool strip_act = (DJ == 16) && (tid < DI * 4);

    if (DJ == 16) {
        if (strip_act) {
            m_s = tid >> 2; g_s = tid & 3;
            rowoff  = gidx<DI>(T1, T2, m_s) * NP;
            colbase = pair_idx(4 * t1 + g_s, 4 * t2);
            const float* p = rho + rowoff + colbase;
            r4.x = __ldg(p); r4.y = __ldg(p + 1); r4.z = __ldg(p + 2); r4.w = __ldg(p + 3);
        }
    } else {
        #pragma unroll
        for (int k = 0; k < 2; k++) {
            int e = tid + 64 * k;
            if (e < DI * 6) {
                int m = e / 6, c = e % 6;
                rs[k] = __ldg(rho + gidx<DI>(T1, T2, m) * NP + gidx<6>(t1, t2, c));
            }
        }
    }

    // ---------------- compose V under the load latency -----------------------
    compose_V(tid, thetas, sV);
    __syncthreads();                         // sV published

    // ---------------- commit gathered block to smem --------------------------
    if (DJ == 16) {
        if (strip_act)
            *reinterpret_cast<float4*>(&bufA[m_s][4 * g_s]) = r4;
    } else {
        #pragma unroll
        for (int k = 0; k < 2; k++) {
            int e = tid + 64 * k;
            if (e < DI * 6) bufA[e / 6][e % 6] = rs[k];
        }
    }
    __syncthreads();                         // bufA ready

    // ---------------- LEFT: bufB = B_I * bufA (fused Kronecker) -------------
    if (DJ == 16) {
        if (strip_act) {
            float4 acc = {0.f, 0.f, 0.f, 0.f};
            if (DI == 16) {
                const float* V1 = sV[T1 >> 2];
                const float* V2 = sV[T2 >> 2];
                const int al = m_s >> 2, be = m_s & 3;
                #pragma unroll
                for (int ap = 0; ap < 4; ap++) {
                    float4 s2 = {0.f, 0.f, 0.f, 0.f};
                    #pragma unroll
                    for (int bp = 0; bp < 4; bp++) {
                        float4 x = *reinterpret_cast<const float4*>(&bufA[ap * 4 + bp][4 * g_s]);
                        float w = V2[be * 4 + bp];
                        s2.x += w * x.x; s2.y += w * x.y; s2.z += w * x.z; s2.w += w * x.w;
                    }
                    float w1 = V1[al * 4 + ap];
                    acc.x += w1 * s2.x; acc.y += w1 * s2.y; acc.z += w1 * s2.z; acc.w += w1 * s2.w;
                }
            } else {
                const float* U = sV[T1 >> 2];
                #pragma unroll
                for (int n = 0; n < 6; n++) {
                    float w = went(U, m_s, n);
                    float4 x = *reinterpret_cast<const float4*>(&bufA[n][4 * g_s]);
                    acc.x += w * x.x; acc.y += w * x.y; acc.z += w * x.z; acc.w += w * x.w;
                }
            }
            *reinterpret_cast<float4*>(&bufB[m_s][4 * g_s]) = acc;
        }
    } else {
        #pragma unroll
        for (int k = 0; k < 2; k++) {
            int e = tid + 64 * k;
            if (e < DI * 6) {
                int m = e / 6, c = e % 6;
                float acc = 0.f;
                if (DI == 16) {
                    const float* V1 = sV[T1 >> 2];
                    const float* V2 = sV[T2 >> 2];
                    const int al = m >> 2, be = m & 3;
                    #pragma unroll
                    for (int ap = 0; ap < 4; ap++) {
                        float s2 = 0.f;
                        #pragma unroll
                        for (int bp = 0; bp < 4; bp++)
                            s2 += V2[be * 4 + bp] * bufA[ap * 4 + bp][c];
                        acc += V1[al * 4 + ap] * s2;
                    }
                } else {
                    const float* U = sV[T1 >> 2];
                    #pragma unroll
                    for (int n = 0; n < 6; n++)
                        acc += went(U, m, n) * bufA[n][c];
                }
                bufB[m][c] = acc;
            }
        }
    }
    __syncthreads();                         // bufB ready

    // ---------------- RIGHT: out = bufB * B_J^T + store ----------------------
    if (DJ == 16) {
        if (strip_act) {
            const float* U1 = sV[t1 >> 2];
            const float* U2 = sV[t2 >> 2];
            float4 y[4];
            #pragma unroll
            for (int gp = 0; gp < 4; gp++)
                y[gp] = *reinterpret_cast<const float4*>(&bufB[m_s][4 * gp]);
            float4 o = {0.f, 0.f, 0.f, 0.f};
            #pragma unroll
            for (int gp = 0; gp < 4; gp++) {
                float s0 = U2[0]  * y[gp].x + U2[1]  * y[gp].y + U2[2]  * y[gp].z + U2[3]  * y[gp].w;
                float s1 = U2[4]  * y[gp].x + U2[5]  * y[gp].y + U2[6]  * y[gp].z + U2[7]  * y[gp].w;
                float s2 = U2[8]  * y[gp].x + U2[9]  * y[gp].y + U2[10] * y[gp].z + U2[11] * y[gp].w;
                float s3 = U2[12] * y[gp].x + U2[13] * y[gp].y + U2[14] * y[gp].z + U2[15] * y[gp].w;
                float w1 = U1[g_s * 4 + gp];
                o.x += w1 * s0; o.y += w1 * s1; o.z += w1 * s2; o.w += w1 * s3;
            }
            float* p = out + rowoff + colbase;
            p[0] = o.x; p[1] = o.y; p[2] = o.z; p[3] = o.w;
        }
    } else {
        const float* U = sV[t1 >> 2];
        #pragma unroll
        for (int k = 0; k < 2; k++) {
            int e = tid + 64 * k;
            if (e < DI * 6) {
                int m = e / 6, c = e % 6;
                float acc = 0.f;
                #pragma unroll
                for (int n = 0; n < 6; n++)
                    acc += went(U, c, n) * bufB[m][n];
                out[gidx<DI>(T1, T2, m) * NP + gidx<6>(t1, t2, c)] = acc;
            }
        }
    }
}

__global__ void __launch_bounds__(64, 16)
rbs_pair_kernel(const float* __restrict__ rho, float* __restrict__ out,
                const float* __restrict__ thetas)
{
    __shared__ float sV[2][16];
    __shared__ __align__(16) float bufA[16][20];
    __shared__ __align__(16) float bufB[16][20];

    const int tid = threadIdx.x;
    const int I = blockIdx.x / 36, J = blockIdx.x % 36;

    int T1, T2, DI, t1, t2, DJ;
    decode_block(I, T1, T2, DI);
    decode_block(J, t1, t2, DJ);

    if (DI == 16) {
        if (DJ == 16) process<16,16>(rho, out, thetas, T1, T2, t1, t2, tid, sV, bufA, bufB);
        else          process<16, 6>(rho, out, thetas, T1, T2, t1, t2, tid, sV, bufA, bufB);
    } else {
        if (DJ == 16) process< 6,16>(rho, out, thetas, T1, T2, t1, t2, tid, sV, bufA, bufB);
        else          process< 6, 6>(rho, out, thetas, T1, T2, t1, t2, tid, sV, bufA, bufB);
    }
}

extern "C" void kernel_launch(void* const* d_in, const int* in_sizes, int n_in,
                              void* d_out, int out_size) {
    // metadata order: rho, thetas, A_stack, B_stack, C_stack, u_idx, p_idx
    const float* rho    = (const float*)d_in[0];
    const float* thetas = (const float*)d_in[1];
    float* out = (float*)d_out;

    rbs_pair_kernel<<<36 * 36, 64>>>(rho, out, thetas);
}

// round 6
// speedup vs baseline: 1.0220x; 1.0220x over previous
#include <cuda_runtime.h>

// out = M rho M^T on the Hamming-weight-2 basis (N = C(32,2) = 496).
// M block-diagonal over 36 pair-blocks; only TWO distinct 4x4 tile matrices
// (V_row: params 0-5, V_col: params 6-11), fixed pyramid order {0,1,0,2,1,0}.
//   cross block (t1<t2): dim 16, B = V_t1 (x) V_t2
//   diag  block (t):     dim 6,  B = Lambda^2(V_t) = W
// Kernel 1 (setup, 1 CTA): compose V and W into __device__ globals.
// Kernel 2 (main, 1296 CTAs x 64 thr): one (I,J) block each, V/W via __ldg,
// rho gather issued first, 2 barriers total.

#define NP 496

__device__ __align__(16) float gV[2][16];
__device__ __align__(16) float gW[2][36];

__device__ __forceinline__ int pair_idx(int a, int b) {
    return a * 31 - (a * (a - 1)) / 2 + (b - a - 1);
}

__device__ __forceinline__ void decode_block(int B, int& t1, int& t2, int& dim) {
    if (B < 28) {
        int rem = B, a = 0;
        while (rem >= 7 - a) { rem -= 7 - a; a++; }
        t1 = a; t2 = a + 1 + rem; dim = 16;
    } else {
        t1 = B - 28; t2 = t1; dim = 6;
    }
}

// P1 = {0,0,0,1,1,2}, P2 = {1,2,3,2,3,3}, 3 bits/entry
#define P1W 0x11200
#define P2W 0x1B4D1
__device__ __forceinline__ int p1of(int m) { return (P1W >> (3 * m)) & 7; }
__device__ __forceinline__ int p2of(int m) { return (P2W >> (3 * m)) & 7; }

template <int D>
__device__ __forceinline__ int gidx(int t1, int t2, int m) {
    if (D == 16) return pair_idx(4 * t1 + (m >> 2), 4 * t2 + (m & 3));
    return pair_idx(4 * t1 + p1of(m), 4 * t1 + p2of(m));
}

// ---------------------------------------------------------------------------
// Setup kernel: compose the two tile matrices and their Lambda^2 forms once.
// ---------------------------------------------------------------------------
__global__ void rbs_setup_kernel(const float* __restrict__ thetas)
{
    const int tid = threadIdx.x;
    if (tid < 2) {
        float v[4][4] = {{1,0,0,0},{0,1,0,0},{0,0,1,0},{0,0,0,1}};
        const int jseq[6] = {0, 1, 0, 2, 1, 0};
        #pragma unroll
        for (int gi = 0; gi < 6; gi++) {
            float s, c;
            sincosf(thetas[tid * 6 + gi], &s, &c);
            const int j = jseq[gi];
            #pragma unroll
            for (int k = 0; k < 4; k++) {
                float a = v[j][k], b = v[j + 1][k];
                v[j][k]     = c * a + s * b;
                v[j + 1][k] = c * b - s * a;
            }
        }
        #pragma unroll
        for (int r = 0; r < 4; r++)
            #pragma unroll
            for (int c = 0; c < 4; c++) gV[tid][r * 4 + c] = v[r][c];
    }
    __syncthreads();
    if (tid < 72) {
        int side = tid / 36, mn = tid % 36, m = mn / 6, n = mn % 6;
        int a = p1of(m), b = p2of(m), g = p1of(n), d = p2of(n);
        const float* V = gV[side];
        gW[side][mn] = V[a * 4 + g] * V[b * 4 + d] - V[a * 4 + d] * V[b * 4 + g];
    }
}

// ---------------------------------------------------------------------------
// Main kernel
// ---------------------------------------------------------------------------
__device__ __forceinline__ float4 ldgV(int tile, int row) {
    return __ldg(reinterpret_cast<const float4*>(&gV[tile >> 2][row * 4]));
}

template <int DI, int DJ>
__device__ __forceinline__ void process(
    const float* __restrict__ rho, float* __restrict__ out,
    int T1, int T2, int t1, int t2, int tid,
    float (*bufA)[20], float (*bufB)[20])
{
    if (DJ == 16) {
        // strip ownership: thread -> (row m_s, 4-col group g_s)
        const bool act = (tid < DI * 4);
        int m_s = tid >> 2, g_s = tid & 3, rowoff = 0, colbase = 0;
        float4 r4;
        if (act) {
            rowoff  = gidx<DI>(T1, T2, m_s) * NP;
            colbase = pair_idx(4 * t1 + g_s, 4 * t2);
            const float* p = rho + rowoff + colbase;
            r4.x = __ldg(p); r4.y = __ldg(p + 1); r4.z = __ldg(p + 2); r4.w = __ldg(p + 3);
            *reinterpret_cast<float4*>(&bufA[m_s][4 * g_s]) = r4;
        }
        __syncthreads();                      // bufA ready

        // LEFT fused: bufB = B_I * bufA
        if (act) {
            float4 acc = {0.f, 0.f, 0.f, 0.f};
            if (DI == 16) {
                const float4 V1r = ldgV(T1, m_s >> 2);
                const float4 V2r = ldgV(T2, m_s & 3);
                const float v1[4] = {V1r.x, V1r.y, V1r.z, V1r.w};
                const float v2[4] = {V2r.x, V2r.y, V2r.z, V2r.w};
                #pragma unroll
                for (int ap = 0; ap < 4; ap++) {
                    float4 s2 = {0.f, 0.f, 0.f, 0.f};
                    #pragma unroll
                    for (int bp = 0; bp < 4; bp++) {
                        float4 x = *reinterpret_cast<const float4*>(&bufA[ap * 4 + bp][4 * g_s]);
                        s2.x += v2[bp] * x.x; s2.y += v2[bp] * x.y;
                        s2.z += v2[bp] * x.z; s2.w += v2[bp] * x.w;
                    }
                    acc.x += v1[ap] * s2.x; acc.y += v1[ap] * s2.y;
                    acc.z += v1[ap] * s2.z; acc.w += v1[ap] * s2.w;
                }
            } else {
                const float* Wr = &gW[T1 >> 2][m_s * 6];
                #pragma unroll
                for (int n = 0; n < 6; n++) {
                    float w = __ldg(Wr + n);
                    float4 x = *reinterpret_cast<const float4*>(&bufA[n][4 * g_s]);
                    acc.x += w * x.x; acc.y += w * x.y; acc.z += w * x.z; acc.w += w * x.w;
                }
            }
            *reinterpret_cast<float4*>(&bufB[m_s][4 * g_s]) = acc;
        }
        __syncthreads();                      // bufB ready

        // RIGHT fused: out = bufB * B_J^T
        if (act) {
            const float4 U1r = ldgV(t1, g_s);
            const float u1[4] = {U1r.x, U1r.y, U1r.z, U1r.w};
            float4 U2r[4];
            #pragma unroll
            for (int r = 0; r < 4; r++) U2r[r] = ldgV(t2, r);
            float4 o = {0.f, 0.f, 0.f, 0.f};
            #pragma unroll
            for (int gp = 0; gp < 4; gp++) {
                float4 y = *reinterpret_cast<const float4*>(&bufB[m_s][4 * gp]);
                float s0 = U2r[0].x * y.x + U2r[0].y * y.y + U2r[0].z * y.z + U2r[0].w * y.w;
                float s1 = U2r[1].x * y.x + U2r[1].y * y.y + U2r[1].z * y.z + U2r[1].w * y.w;
                float s2 = U2r[2].x * y.x + U2r[2].y * y.y + U2r[2].z * y.z + U2r[2].w * y.w;
                float s3 = U2r[3].x * y.x + U2r[3].y * y.y + U2r[3].z * y.z + U2r[3].w * y.w;
                o.x += u1[gp] * s0; o.y += u1[gp] * s1;
                o.z += u1[gp] * s2; o.w += u1[gp] * s3;
            }
            float* p = out + rowoff + colbase;
            p[0] = o.x; p[1] = o.y; p[2] = o.z; p[3] = o.w;
        }
    } else {
        // DJ == 6: scalar elements, up to 2 per thread
        #pragma unroll
        for (int k = 0; k < 2; k++) {
            int e = tid + 64 * k;
            if (e < DI * 6)
                bufA[e / 6][e % 6] = __ldg(rho + gidx<DI>(T1, T2, e / 6) * NP
                                               + gidx<6>(t1, t2, e % 6));
        }
        __syncthreads();

        #pragma unroll
        for (int k = 0; k < 2; k++) {
            int e = tid + 64 * k;
            if (e < DI * 6) {
                int m = e / 6, c = e % 6;
                float acc = 0.f;
                if (DI == 16) {
                    const float4 V1r = ldgV(T1, m >> 2);
                    const float4 V2r = ldgV(T2, m & 3);
                    const float v1[4] = {V1r.x, V1r.y, V1r.z, V1r.w};
                    const float v2[4] = {V2r.x, V2r.y, V2r.z, V2r.w};
                    #pragma unroll
                    for (int ap = 0; ap < 4; ap++) {
                        float s2 = 0.f;
                        #pragma unroll
                        for (int bp = 0; bp < 4; bp++)
                            s2 += v2[bp] * bufA[ap * 4 + bp][c];
                        acc += v1[ap] * s2;
                    }
                } else {
                    const float* Wr = &gW[T1 >> 2][m * 6];
                    #pragma unroll
                    for (int n = 0; n < 6; n++)
                        acc += __ldg(Wr + n) * bufA[n][c];
                }
                bufB[m][c] = acc;
            }
        }
        __syncthreads();

        #pragma unroll
        for (int k = 0; k < 2; k++) {
            int e = tid + 64 * k;
            if (e < DI * 6) {
                int m = e / 6, c = e % 6;
                const float* Wr = &gW[t1 >> 2][c * 6];
                float acc = 0.f;
                #pragma unroll
                for (int n = 0; n < 6; n++)
                    acc += __ldg(Wr + n) * bufB[m][n];
                out[gidx<DI>(T1, T2, m) * NP + gidx<6>(t1, t2, c)] = acc;
            }
        }
    }
}

__global__ void __launch_bounds__(64, 16)
rbs_pair_kernel(const float* __restrict__ rho, float* __restrict__ out)
{
    __shared__ __align__(16) float bufA[16][20];
    __shared__ __align__(16) float bufB[16][20];

    const int tid = threadIdx.x;
    const int I = blockIdx.x / 36, J = blockIdx.x % 36;

    int T1, T2, DI, t1, t2, DJ;
    decode_block(I, T1, T2, DI);
    decode_block(J, t1, t2, DJ);

    if (DI == 16) {
        if (DJ == 16) process<16,16>(rho, out, T1, T2, t1, t2, tid, bufA, bufB);
        else          process<16, 6>(rho, out, T1, T2, t1, t2, tid, bufA, bufB);
    } else {
        if (DJ == 16) process< 6,16>(rho, out, T1, T2, t1, t2, tid, bufA, bufB);
        else          process< 6, 6>(rho, out, T1, T2, t1, t2, tid, bufA, bufB);
    }
}

extern "C" void kernel_launch(void* const* d_in, const int* in_sizes, int n_in,
                              void* d_out, int out_size) {
    // metadata order: rho, thetas, A_stack, B_stack, C_stack, u_idx, p_idx
    const float* rho    = (const float*)d_in[0];
    const float* thetas = (const float*)d_in[1];
    float* out = (float*)d_out;

    rbs_setup_kernel<<<1, 72>>>(thetas);
    rbs_pair_kernel<<<36 * 36, 64>>>(rho, out);
}

// round 7
// speedup vs baseline: 1.0295x; 1.0074x over previous
#include <cuda_runtime.h>

// out = M rho M^T on the Hamming-weight-2 basis (N = C(32,2) = 496).
// M block-diagonal over 36 pair-blocks; only TWO distinct 4x4 tile matrices
// (V_row: params 0-5, V_col: params 6-11), fixed pyramid order {0,1,0,2,1,0}.
//   cross block (t1<t2): dim 16, B = V_t1 (x) V_t2
//   diag  block (t):     dim 6,  B = Lambda^2(V_t) = W
// Kernel 1 (setup, 1 CTA): compose V and W into __device__ globals.
// Kernel 2 (main, 1296 CTAs x 64 thr, PDL): issues the rho gather BEFORE
// cudaGridDependencySynchronize() so the setup kernel + launch gap hide
// under the gather's DRAM latency. 2 barriers per CTA.

#define NP 496

__device__ __align__(16) float gV[2][16];
__device__ __align__(16) float gW[2][36];

__device__ __forceinline__ int pair_idx(int a, int b) {
    return a * 31 - (a * (a - 1)) / 2 + (b - a - 1);
}

__device__ __forceinline__ void decode_block(int B, int& t1, int& t2, int& dim) {
    if (B < 28) {
        int rem = B, a = 0;
        while (rem >= 7 - a) { rem -= 7 - a; a++; }
        t1 = a; t2 = a + 1 + rem; dim = 16;
    } else {
        t1 = B - 28; t2 = t1; dim = 6;
    }
}

// P1 = {0,0,0,1,1,2}, P2 = {1,2,3,2,3,3}, 3 bits/entry
#define P1W 0x11200
#define P2W 0x1B4D1
__device__ __forceinline__ int p1of(int m) { return (P1W >> (3 * m)) & 7; }
__device__ __forceinline__ int p2of(int m) { return (P2W >> (3 * m)) & 7; }

template <int D>
__device__ __forceinline__ int gidx(int t1, int t2, int m) {
    if (D == 16) return pair_idx(4 * t1 + (m >> 2), 4 * t2 + (m & 3));
    return pair_idx(4 * t1 + p1of(m), 4 * t1 + p2of(m));
}

// ---------------------------------------------------------------------------
// Setup kernel
// ---------------------------------------------------------------------------
__global__ void rbs_setup_kernel(const float* __restrict__ thetas)
{
    const int tid = threadIdx.x;
    if (tid < 2) {
        float v[4][4] = {{1,0,0,0},{0,1,0,0},{0,0,1,0},{0,0,0,1}};
        const int jseq[6] = {0, 1, 0, 2, 1, 0};
        #pragma unroll
        for (int gi = 0; gi < 6; gi++) {
            float s, c;
            sincosf(thetas[tid * 6 + gi], &s, &c);
            const int j = jseq[gi];
            #pragma unroll
            for (int k = 0; k < 4; k++) {
                float a = v[j][k], b = v[j + 1][k];
                v[j][k]     = c * a + s * b;
                v[j + 1][k] = c * b - s * a;
            }
        }
        #pragma unroll
        for (int r = 0; r < 4; r++)
            #pragma unroll
            for (int c = 0; c < 4; c++) gV[tid][r * 4 + c] = v[r][c];
    }
    __syncthreads();
    if (tid < 72) {
        int side = tid / 36, mn = tid % 36, m = mn / 6, n = mn % 6;
        int a = p1of(m), b = p2of(m), g = p1of(n), d = p2of(n);
        const float* V = gV[side];
        gW[side][mn] = V[a * 4 + g] * V[b * 4 + d] - V[a * 4 + d] * V[b * 4 + g];
    }
}

// ---------------------------------------------------------------------------
// Main kernel
// ---------------------------------------------------------------------------
__device__ __forceinline__ float4 ldV4(int tile, int row) {
    return *reinterpret_cast<const float4*>(&gV[tile >> 2][row * 4]);
}

template <int DI, int DJ>
__device__ __forceinline__ void process(
    const float* __restrict__ rho, float* __restrict__ out,
    int T1, int T2, int t1, int t2, int tid,
    float (*bufA)[20], float (*bufB)[20])
{
    if (DJ == 16) {
        // strip ownership: thread -> (row m_s, 4-col group g_s)
        const bool act = (tid < DI * 4);
        int m_s = tid >> 2, g_s = tid & 3, rowoff = 0, colbase = 0;
        if (act) {
            rowoff  = gidx<DI>(T1, T2, m_s) * NP;
            colbase = pair_idx(4 * t1 + g_s, 4 * t2);
            const float* p = rho + rowoff + colbase;
            float4 r4;
            r4.x = __ldg(p); r4.y = __ldg(p + 1); r4.z = __ldg(p + 2); r4.w = __ldg(p + 3);
            *reinterpret_cast<float4*>(&bufA[m_s][4 * g_s]) = r4;
        }
        cudaGridDependencySynchronize();      // gV / gW now valid
        __syncthreads();                      // bufA ready

        // LEFT fused: bufB = B_I * bufA
        if (act) {
            float4 acc = {0.f, 0.f, 0.f, 0.f};
            if (DI == 16) {
                const float4 V1r = ldV4(T1, m_s >> 2);
                const float4 V2r = ldV4(T2, m_s & 3);
                const float v1[4] = {V1r.x, V1r.y, V1r.z, V1r.w};
                const float v2[4] = {V2r.x, V2r.y, V2r.z, V2r.w};
                #pragma unroll
                for (int ap = 0; ap < 4; ap++) {
                    float4 s2 = {0.f, 0.f, 0.f, 0.f};
                    #pragma unroll
                    for (int bp = 0; bp < 4; bp++) {
                        float4 x = *reinterpret_cast<const float4*>(&bufA[ap * 4 + bp][4 * g_s]);
                        s2.x += v2[bp] * x.x; s2.y += v2[bp] * x.y;
                        s2.z += v2[bp] * x.z; s2.w += v2[bp] * x.w;
                    }
                    acc.x += v1[ap] * s2.x; acc.y += v1[ap] * s2.y;
                    acc.z += v1[ap] * s2.z; acc.w += v1[ap] * s2.w;
                }
            } else {
                const float* Wr = &gW[T1 >> 2][m_s * 6];
                #pragma unroll
                for (int n = 0; n < 6; n++) {
                    float w = Wr[n];
                    float4 x = *reinterpret_cast<const float4*>(&bufA[n][4 * g_s]);
                    acc.x += w * x.x; acc.y += w * x.y; acc.z += w * x.z; acc.w += w * x.w;
                }
            }
            *reinterpret_cast<float4*>(&bufB[m_s][4 * g_s]) = acc;
        }
        __syncthreads();                      // bufB ready

        // RIGHT fused: out = bufB * B_J^T
        if (act) {
            const float4 U1r = ldV4(t1, g_s);
            const float u1[4] = {U1r.x, U1r.y, U1r.z, U1r.w};
            float4 U2r[4];
            #pragma unroll
            for (int r = 0; r < 4; r++) U2r[r] = ldV4(t2, r);
            float4 o = {0.f, 0.f, 0.f, 0.f};
            #pragma unroll
            for (int gp = 0; gp < 4; gp++) {
                float4 y = *reinterpret_cast<const float4*>(&bufB[m_s][4 * gp]);
                float s0 = U2r[0].x * y.x + U2r[0].y * y.y + U2r[0].z * y.z + U2r[0].w * y.w;
                float s1 = U2r[1].x * y.x + U2r[1].y * y.y + U2r[1].z * y.z + U2r[1].w * y.w;
                float s2 = U2r[2].x * y.x + U2r[2].y * y.y + U2r[2].z * y.z + U2r[2].w * y.w;
                float s3 = U2r[3].x * y.x + U2r[3].y * y.y + U2r[3].z * y.z + U2r[3].w * y.w;
                o.x += u1[gp] * s0; o.y += u1[gp] * s1;
                o.z += u1[gp] * s2; o.w += u1[gp] * s3;
            }
            float* p = out + rowoff + colbase;
            p[0] = o.x; p[1] = o.y; p[2] = o.z; p[3] = o.w;
        }
    } else {
        // DJ == 6: scalar elements, up to 2 per thread
        #pragma unroll
        for (int k = 0; k < 2; k++) {
            int e = tid + 64 * k;
            if (e < DI * 6)
                bufA[e / 6][e % 6] = __ldg(rho + gidx<DI>(T1, T2, e / 6) * NP
                                               + gidx<6>(t1, t2, e % 6));
        }
        cudaGridDependencySynchronize();
        __syncthreads();

        #pragma unroll
        for (int k = 0; k < 2; k++) {
            int e = tid + 64 * k;
            if (e < DI * 6) {
                int m = e / 6, c = e % 6;
                float acc = 0.f;
                if (DI == 16) {
                    const float4 V1r = ldV4(T1, m >> 2);
                    const float4 V2r = ldV4(T2, m & 3);
                    const float v1[4] = {V1r.x, V1r.y, V1r.z, V1r.w};
                    const float v2[4] = {V2r.x, V2r.y, V2r.z, V2r.w};
                    #pragma unroll
                    for (int ap = 0; ap < 4; ap++) {
                        float s2 = 0.f;
                        #pragma unroll
                        for (int bp = 0; bp < 4; bp++)
                            s2 += v2[bp] * bufA[ap * 4 + bp][c];
                        acc += v1[ap] * s2;
                    }
                } else {
                    const float* Wr = &gW[T1 >> 2][m * 6];
                    #pragma unroll
                    for (int n = 0; n < 6; n++)
                        acc += Wr[n] * bufA[n][c];
                }
                bufB[m][c] = acc;
            }
        }
        __syncthreads();

        #pragma unroll
        for (int k = 0; k < 2; k++) {
            int e = tid + 64 * k;
            if (e < DI * 6) {
                int m = e / 6, c = e % 6;
                const float* Wr = &gW[t1 >> 2][c * 6];
                float acc = 0.f;
                #pragma unroll
                for (int n = 0; n < 6; n++)
                    acc += Wr[n] * bufB[m][n];
                out[gidx<DI>(T1, T2, m) * NP + gidx<6>(t1, t2, c)] = acc;
            }
        }
    }
}

__global__ void __launch_bounds__(64, 16)
rbs_pair_kernel(const float* __restrict__ rho, float* __restrict__ out)
{
    __shared__ __align__(16) float bufA[16][20];
    __shared__ __align__(16) float bufB[16][20];

    const int tid = threadIdx.x;
    const int I = blockIdx.x / 36, J = blockIdx.x % 36;

    int T1, T2, DI, t1, t2, DJ;
    decode_block(I, T1, T2, DI);
    decode_block(J, t1, t2, DJ);

    if (DI == 16) {
        if (DJ == 16) process<16,16>(rho, out, T1, T2, t1, t2, tid, bufA, bufB);
        else          process<16, 6>(rho, out, T1, T2, t1, t2, tid, bufA, bufB);
    } else {
        if (DJ == 16) process< 6,16>(rho, out, T1, T2, t1, t2, tid, bufA, bufB);
        else          process< 6, 6>(rho, out, T1, T2, t1, t2, tid, bufA, bufB);
    }
}

extern "C" void kernel_launch(void* const* d_in, const int* in_sizes, int n_in,
                              void* d_out, int out_size) {
    // metadata order: rho, thetas, A_stack, B_stack, C_stack, u_idx, p_idx
    const float* rho    = (const float*)d_in[0];
    const float* thetas = (const float*)d_in[1];
    float* out = (float*)d_out;

    rbs_setup_kernel<<<1, 72>>>(thetas);

    // Main kernel with programmatic dependent launch: starts while setup is
    // in flight; device code gates gV/gW reads on cudaGridDependencySynchronize.
    cudaLaunchConfig_t cfg = {};
    cfg.gridDim  = dim3(36 * 36, 1, 1);
    cfg.blockDim = dim3(64, 1, 1);
    cfg.dynamicSmemBytes = 0;
    cfg.stream = 0;
    cudaLaunchAttribute attr[1];
    attr[0].id = cudaLaunchAttributeProgrammaticStreamSerialization;
    attr[0].val.programmaticStreamSerializationAllowed = 1;
    cfg.attrs = attr;
    cfg.numAttrs = 1;
    cudaLaunchKernelEx(&cfg, rbs_pair_kernel, rho, out);
}

// round 8
// speedup vs baseline: 1.3413x; 1.3029x over previous
#include <cuda_runtime.h>

// out = M rho M^T on the Hamming-weight-2 basis (N = C(32,2) = 496).
// M block-diagonal over 36 pair-blocks; only TWO distinct 4x4 tile matrices
// (V_row: params 0-5, V_col: params 6-11), fixed pyramid order {0,1,0,2,1,0}.
//   cross block (t1<t2): dim 16, B = V_t1 (x) V_t2
//   diag  block (t):     dim 6,  B = Lambda^2(V_t) = W (computed inline)
// SINGLE kernel, 1296 CTAs x 64 threads. Per CTA:
//   - rho gather issued first (hides everything below)
//   - warp-parallel V compose: 1 sincosf/lane + 6 shuffle-FMA steps
//   - DJ=16 path: ONE barrier; right stage via quad butterfly shuffles
//   - DJ=6 path: 2 barriers (rare: 288/1296 CTAs)

#define NP 496

__device__ __forceinline__ int pair_idx(int a, int b) {
    return a * 31 - (a * (a - 1)) / 2 + (b - a - 1);
}

__device__ __forceinline__ void decode_block(int B, int& t1, int& t2, int& dim) {
    if (B < 28) {
        int rem = B, a = 0;
        while (rem >= 7 - a) { rem -= 7 - a; a++; }
        t1 = a; t2 = a + 1 + rem; dim = 16;
    } else {
        t1 = B - 28; t2 = t1; dim = 6;
    }
}

// P1 = {0,0,0,1,1,2}, P2 = {1,2,3,2,3,3}, 3 bits/entry
#define P1W 0x11200
#define P2W 0x1B4D1
__device__ __forceinline__ int p1of(int m) { return (P1W >> (3 * m)) & 7; }
__device__ __forceinline__ int p2of(int m) { return (P2W >> (3 * m)) & 7; }

template <int D>
__device__ __forceinline__ int gidx(int t1, int t2, int m) {
    if (D == 16) return pair_idx(4 * t1 + (m >> 2), 4 * t2 + (m & 3));
    return pair_idx(4 * t1 + p1of(m), 4 * t1 + p2of(m));
}

// Lambda^2 entry of 4x4 U
__device__ __forceinline__ float went(const float* U, int m, int n) {
    int a = p1of(m), b = p2of(m), g = p1of(n), d = p2of(n);
    return U[a * 4 + g] * U[b * 4 + d] - U[a * 4 + d] * U[b * 4 + g];
}

// Warp-parallel compose: warp w builds V for param group w (6 params).
// Lane l (<16) ends holding V[l>>2][l&3]; lanes 0-5 each do ONE sincosf.
__device__ __forceinline__ void compose_V(int tid, const float* __restrict__ thetas,
                                          float (*sV)[16]) {
    const int w = tid >> 5, lane = tid & 31;
    float s, c;
    sincosf(__ldg(thetas + w * 6 + (lane % 6)), &s, &c);
    const int r = lane >> 2;
    float v = ((lane < 16) && ((lane >> 2) == (lane & 3))) ? 1.f : 0.f;
    const int jseq[6] = {0, 1, 0, 2, 1, 0};
    #pragma unroll
    for (int gi = 0; gi < 6; gi++) {
        const int j = jseq[gi];
        float cg = __shfl_sync(0xFFFFFFFFu, c, gi);
        float sg = __shfl_sync(0xFFFFFFFFu, s, gi);
        float vu = __shfl_sync(0xFFFFFFFFu, v, (lane + 4) & 31);
        float vd = __shfl_sync(0xFFFFFFFFu, v, (lane - 4) & 31);
        if (r == j)            v = cg * v + sg * vu;
        else if (r == j + 1)   v = cg * v - sg * vd;
    }
    if (lane < 16) sV[w][lane] = v;
}

__device__ __forceinline__ float4 shflx4(float4 a, int m) {
    float4 r;
    r.x = __shfl_xor_sync(0xFFFFFFFFu, a.x, m);
    r.y = __shfl_xor_sync(0xFFFFFFFFu, a.y, m);
    r.z = __shfl_xor_sync(0xFFFFFFFFu, a.z, m);
    r.w = __shfl_xor_sync(0xFFFFFFFFu, a.w, m);
    return r;
}

__device__ __forceinline__ void accum_right(float4& o, const float4* U2r,
                                            float cf, float4 y) {
    float s0 = U2r[0].x * y.x + U2r[0].y * y.y + U2r[0].z * y.z + U2r[0].w * y.w;
    float s1 = U2r[1].x * y.x + U2r[1].y * y.y + U2r[1].z * y.z + U2r[1].w * y.w;
    float s2 = U2r[2].x * y.x + U2r[2].y * y.y + U2r[2].z * y.z + U2r[2].w * y.w;
    float s3 = U2r[3].x * y.x + U2r[3].y * y.y + U2r[3].z * y.z + U2r[3].w * y.w;
    o.x += cf * s0; o.y += cf * s1; o.z += cf * s2; o.w += cf * s3;
}

// ---------------- DJ == 16 path: one barrier, shuffle-based right stage -----
template <int DI>
__device__ __forceinline__ void path_cross(
    const float* __restrict__ rho, float* __restrict__ out,
    const float* __restrict__ thetas,
    int T1, int T2, int t1, int t2, int tid,
    float (*sV)[16], float (*bufA)[20])
{
    const bool act = (tid < DI * 4);
    const int m_s = tid >> 2, g_s = tid & 3;
    int rowoff = 0, colbase = 0;
    float4 r4 = {0.f, 0.f, 0.f, 0.f};
    if (act) {
        rowoff  = gidx<DI>(T1, T2, m_s) * NP;
        colbase = pair_idx(4 * t1 + g_s, 4 * t2);
        const float* p = rho + rowoff + colbase;
        r4.x = __ldg(p); r4.y = __ldg(p + 1); r4.z = __ldg(p + 2); r4.w = __ldg(p + 3);
    }
    compose_V(tid, thetas, sV);              // overlaps the gather
    if (act) *reinterpret_cast<float4*>(&bufA[m_s][4 * g_s]) = r4;
    __syncthreads();                         // sV + bufA ready

    // LEFT fused: acc = (B_I * bufA) strip (m_s, cols 4g..4g+3)
    float4 acc = {0.f, 0.f, 0.f, 0.f};
    if (DI == 16) {
        const float4 V1r = *reinterpret_cast<const float4*>(&sV[T1 >> 2][(m_s >> 2) * 4]);
        const float4 V2r = *reinterpret_cast<const float4*>(&sV[T2 >> 2][(m_s & 3) * 4]);
        const float v1[4] = {V1r.x, V1r.y, V1r.z, V1r.w};
        const float v2[4] = {V2r.x, V2r.y, V2r.z, V2r.w};
        #pragma unroll
        for (int ap = 0; ap < 4; ap++) {
            float4 s2 = {0.f, 0.f, 0.f, 0.f};
            #pragma unroll
            for (int bp = 0; bp < 4; bp++) {
                float4 x = *reinterpret_cast<const float4*>(&bufA[ap * 4 + bp][4 * g_s]);
                s2.x += v2[bp] * x.x; s2.y += v2[bp] * x.y;
                s2.z += v2[bp] * x.z; s2.w += v2[bp] * x.w;
            }
            acc.x += v1[ap] * s2.x; acc.y += v1[ap] * s2.y;
            acc.z += v1[ap] * s2.z; acc.w += v1[ap] * s2.w;
        }
    } else {
        const float* U = sV[T1 >> 2];
        const int mm = m_s % 6;              // clamp for inactive lanes
        #pragma unroll
        for (int n = 0; n < 6; n++) {
            float w = went(U, mm, n);
            float4 x = *reinterpret_cast<const float4*>(&bufA[n][4 * g_s]);
            acc.x += w * x.x; acc.y += w * x.y; acc.z += w * x.z; acc.w += w * x.w;
        }
    }

    // quad butterfly: collect the 4 float4s of this row (gp = g, g^1, g^2, g^3)
    float4 A = acc;
    float4 B = shflx4(A, 1);
    float4 C = shflx4(A, 2);
    float4 D = shflx4(B, 2);

    // RIGHT fused: out strip = row(B_J applied) at (m_s, 4g_s..4g_s+3)
    const float* U1 = sV[t1 >> 2];
    float4 U2r[4];
    #pragma unroll
    for (int r = 0; r < 4; r++)
        U2r[r] = *reinterpret_cast<const float4*>(&sV[t2 >> 2][r * 4]);
    float4 o = {0.f, 0.f, 0.f, 0.f};
    accum_right(o, U2r, U1[g_s * 4 + g_s],       A);
    accum_right(o, U2r, U1[g_s * 4 + (g_s ^ 1)], B);
    accum_right(o, U2r, U1[g_s * 4 + (g_s ^ 2)], C);
    accum_right(o, U2r, U1[g_s * 4 + (g_s ^ 3)], D);

    if (act) {
        float* p = out + rowoff + colbase;
        p[0] = o.x; p[1] = o.y; p[2] = o.z; p[3] = o.w;
    }
}

// ---------------- DJ == 6 path (288 CTAs): smem 3-stage, 2 barriers ---------
template <int DI>
__device__ __forceinline__ void path_diag(
    const float* __restrict__ rho, float* __restrict__ out,
    const float* __restrict__ thetas,
    int T1, int T2, int t1, int tid,
    float (*sV)[16], float (*bufA)[20], float (*bufB)[20])
{
    float rs[2];
    #pragma unroll
    for (int k = 0; k < 2; k++) {
        int e = tid + 64 * k;
        if (e < DI * 6)
            rs[k] = __ldg(rho + gidx<DI>(T1, T2, e / 6) * NP + gidx<6>(t1, t1, e % 6));
    }
    compose_V(tid, thetas, sV);
    #pragma unroll
    for (int k = 0; k < 2; k++) {
        int e = tid + 64 * k;
        if (e < DI * 6) bufA[e / 6][e % 6] = rs[k];
    }
    __syncthreads();

    #pragma unroll
    for (int k = 0; k < 2; k++) {
        int e = tid + 64 * k;
        if (e < DI * 6) {
            int m = e / 6, c = e % 6;
            float acc = 0.f;
            if (DI == 16) {
                const float4 V1r = *reinterpret_cast<const float4*>(&sV[T1 >> 2][(m >> 2) * 4]);
                const float4 V2r = *reinterpret_cast<const float4*>(&sV[T2 >> 2][(m & 3) * 4]);
                const float v1[4] = {V1r.x, V1r.y, V1r.z, V1r.w};
                const float v2[4] = {V2r.x, V2r.y, V2r.z, V2r.w};
                #pragma unroll
                for (int ap = 0; ap < 4; ap++) {
                    float s2 = 0.f;
                    #pragma unroll
                    for (int bp = 0; bp < 4; bp++)
                        s2 += v2[bp] * bufA[ap * 4 + bp][c];
                    acc += v1[ap] * s2;
                }
            } else {
                const float* U = sV[T1 >> 2];
                #pragma unroll
                for (int n = 0; n < 6; n++)
                    acc += went(U, m, n) * bufA[n][c];
            }
            bufB[m][c] = acc;
        }
    }
    __syncthreads();

    const float* UJ = sV[t1 >> 2];
    #pragma unroll
    for (int k = 0; k < 2; k++) {
        int e = tid + 64 * k;
        if (e < DI * 6) {
            int m = e / 6, c = e % 6;
            float acc = 0.f;
            #pragma unroll
            for (int n = 0; n < 6; n++)
                acc += went(UJ, c, n) * bufB[m][n];
            out[gidx<DI>(T1, T2, m) * NP + gidx<6>(t1, t1, c)] = acc;
        }
    }
}

__global__ void __launch_bounds__(64, 16)
rbs_kernel(const float* __restrict__ rho, float* __restrict__ out,
           const float* __restrict__ thetas)
{
    __shared__ __align__(16) float sV[2][16];
    __shared__ __align__(16) float bufA[16][20];
    __shared__ __align__(16) float bufB[16][20];

    const int tid = threadIdx.x;
    const int I = blockIdx.x / 36, J = blockIdx.x % 36;

    int T1, T2, DI, t1, t2, DJ;
    decode_block(I, T1, T2, DI);
    decode_block(J, t1, t2, DJ);

    if (DJ == 16) {
        if (DI == 16) path_cross<16>(rho, out, thetas, T1, T2, t1, t2, tid, sV, bufA);
        else          path_cross< 6>(rho, out, thetas, T1, T2, t1, t2, tid, sV, bufA);
    } else {
        if (DI == 16) path_diag<16>(rho, out, thetas, T1, T2, t1, tid, sV, bufA, bufB);
        else          path_diag< 6>(rho, out, thetas, T1, T2, t1, tid, sV, bufA, bufB);
    }
}

extern "C" void kernel_launch(void* const* d_in, const int* in_sizes, int n_in,
                              void* d_out, int out_size) {
    // metadata order: rho, thetas, A_stack, B_stack, C_stack, u_idx, p_idx
    const float* rho    = (const float*)d_in[0];
    const float* thetas = (const float*)d_in[1];
    float* out = (float*)d_out;

    rbs_kernel<<<36 * 36, 64>>>(rho, out, thetas);
}